// round 15
// baseline (speedup 1.0000x reference)
#include <cuda_runtime.h>
#include <math.h>
#include <stdint.h>

#define BATCH 64
#define IC 32
#define OC 32
#define NM 64
#define HW 4096
#define CTRLD 512
#define ROWS 4160        // NF(64) + NI(2048) + NO(2048)
#define BR (BATCH * ROWS)
#define OUT_ELEMS (BATCH * OC * HW)

// reduced gates [batch][row] (written directly by tensor ctrl GEMM)
__device__ float g_gates[BR];

__device__ __forceinline__ float tanh_fast(float x) {
    float y;
    asm("tanh.approx.f32 %0, %1;" : "=f"(y) : "f"(x));
    return y;
}
__device__ __forceinline__ float round_tf32(float x) {
    uint32_t h;
    asm("cvt.rna.tf32.f32 %0, %1;" : "=r"(h) : "f"(x));
    return __uint_as_float(h);
}
// a01 = (A[g][tg], A[g][tg+4]); a23 = (A[g+8][tg], A[g+8][tg+4]); b = (B[tg][n], B[tg+4][n])
__device__ __forceinline__ void mma_tf32_f(float* d, float2 a01, float2 a23, float2 b) {
    asm("mma.sync.aligned.m16n8k8.row.col.f32.tf32.tf32.f32 "
        "{%0,%1,%2,%3},{%4,%5,%6,%7},{%8,%9},{%0,%1,%2,%3};"
        : "+f"(d[0]), "+f"(d[1]), "+f"(d[2]), "+f"(d[3])
        : "r"(__float_as_uint(a01.x)), "r"(__float_as_uint(a23.x)),
          "r"(__float_as_uint(a01.y)), "r"(__float_as_uint(a23.y)),
          "r"(__float_as_uint(b.x)),   "r"(__float_as_uint(b.y)));
}
__device__ __forceinline__ void mma_tf32_u(float* d, const uint32_t* a, const uint32_t* b) {
    asm("mma.sync.aligned.m16n8k8.row.col.f32.tf32.tf32.f32 "
        "{%0,%1,%2,%3},{%4,%5,%6,%7},{%8,%9},{%0,%1,%2,%3};"
        : "+f"(d[0]), "+f"(d[1]), "+f"(d[2]), "+f"(d[3])
        : "r"(a[0]), "r"(a[1]), "r"(a[2]), "r"(a[3]), "r"(b[0]), "r"(b[1]));
}

// ---------------------------------------------------------------------------
// Kernel 1: tensor-core ctrl GEMM. g_gates[b][r] = sum_k W[r,k]*controls[b,k].
// grid 260 (16 rows/block), 256 threads (8 warps, each owns 8 batches).
// Exact-W (hi/lo) x tf32-controls: 2 MMAs per k-step. K=512 in 8 chunks of 64,
// double-buffered. W in perm layout (LDS.64 A-frags); sC pad 72 (conflict-free).
// ---------------------------------------------------------------------------
#define WPAD 68
#define CPAD 72

__global__ __launch_bounds__(256) void ctrl_gemm_tc(
    const float* __restrict__ controls,   // [64, 512]
    const float* __restrict__ W)          // [4160, 512]
{
    extern __shared__ float smem[];
    float* sWh = smem;                    // [2][16*68]
    float* sWl = sWh + 2 * 16 * WPAD;     // [2][16*68]
    float* sC  = sWl + 2 * 16 * WPAD;     // [2][64*72]  (rows=k, cols=batch)

    const int r0   = blockIdx.x * 16;
    const int tid  = threadIdx.x;
    const int lane = tid & 31;
    const int w    = tid >> 5;      // 0..7
    const int g    = lane >> 2;     // 0..7
    const int tg   = lane & 3;      // 0..3
    const int n0   = w * 8;         // batch base for this warp

    // W staging coords: one float4 per thread per chunk
    const int swr = tid >> 4;           // 0..15 row
    const int swk = (tid & 15) * 4;     // 0..60 k within chunk
    const float* wp = W + (size_t)(r0 + swr) * CTRLD + swk;
    const int wpos0 = swr * WPAD + (swk >> 3) * 8 + ((swk >> 2) & 1);  // +0,2,4,6

    // C staging coords: 4 float4 per thread per chunk (b-major, k scattered)
    const int cb  = tid & 63;           // batch
    const int ckq = tid >> 6;           // 0..3 ; kq = ckq + it*4
    const float* cp = controls + (size_t)cb * CTRLD + ckq * 4;

    float dh[4] = {}, dl[4] = {};

    // prologue: stage chunk 0
    {
        float4 wv = *(const float4*)wp;
        float vh, vl;
        vh = round_tf32(wv.x); vl = round_tf32(wv.x - vh);
        sWh[wpos0 + 0] = vh; sWl[wpos0 + 0] = vl;
        vh = round_tf32(wv.y); vl = round_tf32(wv.y - vh);
        sWh[wpos0 + 2] = vh; sWl[wpos0 + 2] = vl;
        vh = round_tf32(wv.z); vl = round_tf32(wv.z - vh);
        sWh[wpos0 + 4] = vh; sWl[wpos0 + 4] = vl;
        vh = round_tf32(wv.w); vl = round_tf32(wv.w - vh);
        sWh[wpos0 + 6] = vh; sWl[wpos0 + 6] = vl;

        #pragma unroll
        for (int it = 0; it < 4; it++) {
            float4 cv = *(const float4*)(cp + it * 16);
            int k4 = (ckq + it * 4) * 4;
            sC[(k4 + 0) * CPAD + cb] = round_tf32(cv.x);
            sC[(k4 + 1) * CPAD + cb] = round_tf32(cv.y);
            sC[(k4 + 2) * CPAD + cb] = round_tf32(cv.z);
            sC[(k4 + 3) * CPAD + cb] = round_tf32(cv.w);
        }
    }
    __syncthreads();

    #pragma unroll
    for (int c = 0; c < 8; c++) {
        const int cur = c & 1;
        const int nxt = cur ^ 1;
        float* sWhc = sWh + cur * 16 * WPAD;
        float* sWlc = sWl + cur * 16 * WPAD;
        float* sCc  = sC  + cur * 64 * CPAD;

        // prefetch next chunk
        float4 wv, cv0, cv1, cv2, cv3;
        if (c < 7) {
            wv  = *(const float4*)(wp + (c + 1) * 64);
            cv0 = *(const float4*)(cp + (c + 1) * 64);
            cv1 = *(const float4*)(cp + (c + 1) * 64 + 16);
            cv2 = *(const float4*)(cp + (c + 1) * 64 + 32);
            cv3 = *(const float4*)(cp + (c + 1) * 64 + 48);
        }

        #pragma unroll
        for (int ks = 0; ks < 8; ks++) {
            float2 a01h = *(const float2*)&sWhc[g * WPAD + ks * 8 + tg * 2];
            float2 a23h = *(const float2*)&sWhc[(g + 8) * WPAD + ks * 8 + tg * 2];
            float2 a01l = *(const float2*)&sWlc[g * WPAD + ks * 8 + tg * 2];
            float2 a23l = *(const float2*)&sWlc[(g + 8) * WPAD + ks * 8 + tg * 2];
            float2 bv;
            bv.x = sCc[(ks * 8 + tg)     * CPAD + n0 + g];
            bv.y = sCc[(ks * 8 + tg + 4) * CPAD + n0 + g];
            mma_tf32_f(dh, a01h, a23h, bv);
            mma_tf32_f(dl, a01l, a23l, bv);
        }

        if (c < 7) {
            float* sWhn = sWh + nxt * 16 * WPAD;
            float* sWln = sWl + nxt * 16 * WPAD;
            float* sCn  = sC  + nxt * 64 * CPAD;
            float vh, vl;
            vh = round_tf32(wv.x); vl = round_tf32(wv.x - vh);
            sWhn[wpos0 + 0] = vh; sWln[wpos0 + 0] = vl;
            vh = round_tf32(wv.y); vl = round_tf32(wv.y - vh);
            sWhn[wpos0 + 2] = vh; sWln[wpos0 + 2] = vl;
            vh = round_tf32(wv.z); vl = round_tf32(wv.z - vh);
            sWhn[wpos0 + 4] = vh; sWln[wpos0 + 4] = vl;
            vh = round_tf32(wv.w); vl = round_tf32(wv.w - vh);
            sWhn[wpos0 + 6] = vh; sWln[wpos0 + 6] = vl;

            float4 cvs[4] = {cv0, cv1, cv2, cv3};
            #pragma unroll
            for (int it = 0; it < 4; it++) {
                int k4 = (ckq + it * 4) * 4;
                sCn[(k4 + 0) * CPAD + cb] = round_tf32(cvs[it].x);
                sCn[(k4 + 1) * CPAD + cb] = round_tf32(cvs[it].y);
                sCn[(k4 + 2) * CPAD + cb] = round_tf32(cvs[it].z);
                sCn[(k4 + 3) * CPAD + cb] = round_tf32(cvs[it].w);
            }
            __syncthreads();
        }
    }

    // epilogue: d = dh + dl; scatter to g_gates[b][r]
    const int r1 = r0 + g, r2 = r1 + 8;
    const int b0 = n0 + 2 * tg;
    g_gates[(size_t)b0       * ROWS + r1] = dh[0] + dl[0];
    g_gates[(size_t)(b0 + 1) * ROWS + r1] = dh[1] + dl[1];
    g_gates[(size_t)b0       * ROWS + r2] = dh[2] + dl[2];
    g_gates[(size_t)(b0 + 1) * ROWS + r2] = dh[3] + dl[3];
}

// ---------------------------------------------------------------------------
// Kernel 2: tensor-core vstm (R13 measured-best). Phase 1: exact-A (2 MMA).
// Phase 2: gout tf32 (1 MMA).
// ---------------------------------------------------------------------------
#define PIX_PAD 136

__global__ __launch_bounds__(512, 2) void vstm_main(
    const float* __restrict__ inputs,     // [B, 32, 4096]
    const float* __restrict__ state,      // [B, 64, 4096]
    float* __restrict__ outputs,          // [B, 32, 4096]
    float* __restrict__ new_state)        // [B, 64, 4096]
{
    extern __shared__ float sm[];
    float* s_in   = sm;                          // [32][136] tf32-rounded
    float* s_t    = s_in + 32 * PIX_PAD;         // [64][136] tf32-rounded
    float* s_ginh = s_t + 64 * PIX_PAD;          // [m][36] hi
    float* s_ginl = s_ginh + 64 * 36;            // [m][36] lo
    float* s_goth = s_ginl + 64 * 36;            // [o][68] tf32
    float* s_f    = s_goth + 32 * 68;            // [64] exact

    const int b    = blockIdx.y;
    const int p0   = blockIdx.x * 128;
    const int tid  = threadIdx.x;
    const int lane = tid & 31;
    const int w    = tid >> 5;
    const int g    = lane >> 2;
    const int tg   = lane & 3;

    // ---- stage gates ----
    {
        const float* gc = g_gates + (size_t)b * ROWS;
        for (int i = tid; i < ROWS; i += 512) {
            float v  = gc[i];
            float hi = round_tf32(v);
            if (i < 64) {
                s_f[i] = v;
            } else if (i < 64 + 2048) {
                float lo = round_tf32(v - hi);
                int j = i - 64;
                s_ginh[(j >> 5) * 36 + (j & 31)] = hi;
                s_ginl[(j >> 5) * 36 + (j & 31)] = lo;
            } else {
                int j = i - 2112;
                s_goth[(j >> 6) * 68 + (j & 63)] = hi;
            }
        }
    }

    // ---- stage input tile, tf32-rounded ----
    const float* inb = inputs + (size_t)b * (IC * HW) + p0;
    #pragma unroll
    for (int i = tid; i < 32 * 32; i += 512) {
        int c = i >> 5, p4 = i & 31;
        float4 v = *(const float4*)&inb[c * 4096 + p4 * 4];
        v.x = round_tf32(v.x); v.y = round_tf32(v.y);
        v.z = round_tf32(v.z); v.w = round_tf32(v.w);
        *(float4*)&s_in[c * PIX_PAD + p4 * 4] = v;
    }
    __syncthreads();

    // ==== phase 1: gated(64x128) = gin(64x32) @ in(32x128), exact-A ====
    {
        const int m0 = (w & 3) * 16;
        const int pg = (w >> 2) * 32;
        float d[4][4] = {};

        #pragma unroll
        for (int kk = 0; kk < 4; kk++) {
            const int k0 = kk * 8;
            uint32_t ah[4], al[4];
            ah[0] = __float_as_uint(s_ginh[(m0 + g)     * 36 + k0 + tg]);
            ah[1] = __float_as_uint(s_ginh[(m0 + g + 8) * 36 + k0 + tg]);
            ah[2] = __float_as_uint(s_ginh[(m0 + g)     * 36 + k0 + tg + 4]);
            ah[3] = __float_as_uint(s_ginh[(m0 + g + 8) * 36 + k0 + tg + 4]);
            al[0] = __float_as_uint(s_ginl[(m0 + g)     * 36 + k0 + tg]);
            al[1] = __float_as_uint(s_ginl[(m0 + g + 8) * 36 + k0 + tg]);
            al[2] = __float_as_uint(s_ginl[(m0 + g)     * 36 + k0 + tg + 4]);
            al[3] = __float_as_uint(s_ginl[(m0 + g + 8) * 36 + k0 + tg + 4]);

            #pragma unroll
            for (int u = 0; u < 4; u++) {
                const int pb = pg + u * 8;
                uint32_t bh[2];
                bh[0] = __float_as_uint(s_in[(k0 + tg)     * PIX_PAD + pb + g]);
                bh[1] = __float_as_uint(s_in[(k0 + tg + 4) * PIX_PAD + pb + g]);
                mma_tf32_u(d[u], ah, bh);
                mma_tf32_u(d[u], al, bh);
            }
        }

        const int r1 = m0 + g, r2 = r1 + 8;
        const float f1 = s_f[r1], f2 = s_f[r2];
        const float* stb = state + (size_t)b * (NM * HW) + p0;
        float*       nsb = new_state + (size_t)b * (NM * HW) + p0;

        #pragma unroll
        for (int u = 0; u < 4; u++) {
            const int c2 = pg + u * 8 + 2 * tg;
            float2 st1 = *(const float2*)&stb[(size_t)r1 * 4096 + c2];
            float2 st2 = *(const float2*)&stb[(size_t)r2 * 4096 + c2];
            float2 ns1, ns2;
            ns1.x = fmaf(st1.x, f1, d[u][0]);
            ns1.y = fmaf(st1.y, f1, d[u][1]);
            ns2.x = fmaf(st2.x, f2, d[u][2]);
            ns2.y = fmaf(st2.y, f2, d[u][3]);
            *(float2*)&nsb[(size_t)r1 * 4096 + c2] = ns1;
            *(float2*)&nsb[(size_t)r2 * 4096 + c2] = ns2;
            float2 t1, t2;
            t1.x = round_tf32(tanh_fast(ns1.x));
            t1.y = round_tf32(tanh_fast(ns1.y));
            t2.x = round_tf32(tanh_fast(ns2.x));
            t2.y = round_tf32(tanh_fast(ns2.y));
            *(float2*)&s_t[r1 * PIX_PAD + c2] = t1;
            *(float2*)&s_t[r2 * PIX_PAD + c2] = t2;
        }
    }
    __syncthreads();

    // ==== phase 2: out(32x128) = gout_tf32(32x64) @ t(64x128), 1 MMA ====
    {
        const int o0  = (w & 1) * 16;
        const int pg2 = (w >> 1) * 16;
        float d[2][4] = {};

        #pragma unroll
        for (int kk = 0; kk < 8; kk++) {
            const int k0 = kk * 8;
            uint32_t ah[4];
            ah[0] = __float_as_uint(s_goth[(o0 + g)     * 68 + k0 + tg]);
            ah[1] = __float_as_uint(s_goth[(o0 + g + 8) * 68 + k0 + tg]);
            ah[2] = __float_as_uint(s_goth[(o0 + g)     * 68 + k0 + tg + 4]);
            ah[3] = __float_as_uint(s_goth[(o0 + g + 8) * 68 + k0 + tg + 4]);

            #pragma unroll
            for (int v = 0; v < 2; v++) {
                const int pb = pg2 + v * 8;
                uint32_t bh[2];
                bh[0] = __float_as_uint(s_t[(k0 + tg)     * PIX_PAD + pb + g]);
                bh[1] = __float_as_uint(s_t[(k0 + tg + 4) * PIX_PAD + pb + g]);
                mma_tf32_u(d[v], ah, bh);
            }
        }

        const int r1 = o0 + g, r2 = r1 + 8;
        float* ob = outputs + (size_t)b * (OC * HW) + p0;
        #pragma unroll
        for (int v = 0; v < 2; v++) {
            const int c2 = pg2 + v * 8 + 2 * tg;
            *(float2*)&ob[(size_t)r1 * 4096 + c2] = make_float2(d[v][0], d[v][1]);
            *(float2*)&ob[(size_t)r2 * 4096 + c2] = make_float2(d[v][2], d[v][3]);
        }
    }
}

// ---------------------------------------------------------------------------
extern "C" void kernel_launch(void* const* d_in, const int* in_sizes, int n_in,
                              void* d_out, int out_size) {
    const float* inputs   = (const float*)d_in[0];   // [64,32,64,64]
    const float* state    = (const float*)d_in[1];   // [64,64,64,64]
    const float* controls = (const float*)d_in[2];   // [64,512]
    const float* W        = (const float*)d_in[3];   // [4160,512]

    float* outputs   = (float*)d_out;
    float* new_state = outputs + OUT_ELEMS;

    const size_t smem1 = (2 * 16 * WPAD * 2 + 2 * 64 * CPAD) * sizeof(float);
    cudaFuncSetAttribute(ctrl_gemm_tc, cudaFuncAttributeMaxDynamicSharedMemorySize, (int)smem1);
    ctrl_gemm_tc<<<ROWS / 16, 256, smem1>>>(controls, W);

    const size_t smem2 = (32 * PIX_PAD + 64 * PIX_PAD + 2 * 64 * 36 + 32 * 68 + 64)
                         * sizeof(float);
    cudaFuncSetAttribute(vstm_main, cudaFuncAttributeMaxDynamicSharedMemorySize, (int)smem2);
    vstm_main<<<dim3(HW / 128, BATCH), 512, smem2>>>(inputs, state, outputs, new_state);
}

// round 16
// speedup vs baseline: 1.1037x; 1.1037x over previous
#include <cuda_runtime.h>
#include <math.h>
#include <stdint.h>

#define BATCH 64
#define IC 32
#define OC 32
#define NM 64
#define HW 4096
#define CTRLD 512
#define ROWS 4160        // NF(64) + NI(2048) + NO(2048)
#define KSPLIT 4
#define BR (BATCH * ROWS)
#define OUT_ELEMS (BATCH * OC * HW)

__device__ float g_ctrl[KSPLIT * BR];   // partials [kz][row][batch]
__device__ float g_gates[BR];           // reduced [batch][row]

__device__ __forceinline__ float tanh_fast(float x) {
    float y;
    asm("tanh.approx.f32 %0, %1;" : "=f"(y) : "f"(x));
    return y;
}
__device__ __forceinline__ float round_tf32(float x) {
    uint32_t h;
    asm("cvt.rna.tf32.f32 %0, %1;" : "=r"(h) : "f"(x));
    return __uint_as_float(h);
}
__device__ __forceinline__ void mma_tf32_u(float* d, const uint32_t* a, const uint32_t* b) {
    asm("mma.sync.aligned.m16n8k8.row.col.f32.tf32.tf32.f32 "
        "{%0,%1,%2,%3},{%4,%5,%6,%7},{%8,%9},{%0,%1,%2,%3};"
        : "+f"(d[0]), "+f"(d[1]), "+f"(d[2]), "+f"(d[3])
        : "r"(a[0]), "r"(a[1]), "r"(a[2]), "r"(a[3]), "r"(b[0]), "r"(b[1]));
}
__device__ __forceinline__ uint32_t smem_u32(const void* p) {
    return (uint32_t)__cvta_generic_to_shared(p);
}
__device__ __forceinline__ void cp_async16(uint32_t saddr, const void* gaddr) {
    asm volatile("cp.async.cg.shared.global [%0], [%1], 16;"
                 :: "r"(saddr), "l"(gaddr));
}

// ---------------------------------------------------------------------------
// Kernel 1: ctrl partials = controls @ W.T (grid 65 x 4). R8/R13 config.
// ---------------------------------------------------------------------------
__global__ __launch_bounds__(256) void ctrl_gemm(
    const float* __restrict__ controls,   // [64, 512]
    const float* __restrict__ W)          // [4160, 512]
{
    __shared__ float sW[2][16 * 68];
    __shared__ float sC[2][16 * 68];

    const int r0    = blockIdx.x * 64;
    const int kz    = blockIdx.y;
    const int kbase = kz * (CTRLD / KSPLIT);
    const int tid   = threadIdx.x;
    const int ty    = tid >> 4;
    const int tx    = tid & 15;

    const int sr = tid >> 2;
    const int sk = (tid & 3) * 4;

    const float* wp = W + (size_t)(r0 + sr) * CTRLD + kbase + sk;
    const float* cp = controls + sr * CTRLD + kbase + sk;

    float acc[4][4] = {};

    {
        float4 wv = *(const float4*)wp;
        float4 cv = *(const float4*)cp;
        sW[0][(sk + 0) * 68 + sr] = wv.x;
        sW[0][(sk + 1) * 68 + sr] = wv.y;
        sW[0][(sk + 2) * 68 + sr] = wv.z;
        sW[0][(sk + 3) * 68 + sr] = wv.w;
        sC[0][(sk + 0) * 68 + sr] = cv.x;
        sC[0][(sk + 1) * 68 + sr] = cv.y;
        sC[0][(sk + 2) * 68 + sr] = cv.z;
        sC[0][(sk + 3) * 68 + sr] = cv.w;
    }
    __syncthreads();

    #pragma unroll
    for (int c = 0; c < 8; c++) {
        const int cur = c & 1;
        const int nxt = cur ^ 1;

        float4 wv, cv;
        if (c < 7) {
            wv = *(const float4*)(wp + (c + 1) * 16);
            cv = *(const float4*)(cp + (c + 1) * 16);
        }

        #pragma unroll
        for (int k = 0; k < 16; k++) {
            float4 a  = *(const float4*)&sW[cur][k * 68 + ty * 4];
            float4 bb = *(const float4*)&sC[cur][k * 68 + tx * 4];
            float av[4] = {a.x, a.y, a.z, a.w};
            float bv[4] = {bb.x, bb.y, bb.z, bb.w};
            #pragma unroll
            for (int i = 0; i < 4; i++)
                #pragma unroll
                for (int j = 0; j < 4; j++)
                    acc[i][j] = fmaf(av[i], bv[j], acc[i][j]);
        }

        if (c < 7) {
            sW[nxt][(sk + 0) * 68 + sr] = wv.x;
            sW[nxt][(sk + 1) * 68 + sr] = wv.y;
            sW[nxt][(sk + 2) * 68 + sr] = wv.z;
            sW[nxt][(sk + 3) * 68 + sr] = wv.w;
            sC[nxt][(sk + 0) * 68 + sr] = cv.x;
            sC[nxt][(sk + 1) * 68 + sr] = cv.y;
            sC[nxt][(sk + 2) * 68 + sr] = cv.z;
            sC[nxt][(sk + 3) * 68 + sr] = cv.w;
            __syncthreads();
        }
    }

    #pragma unroll
    for (int i = 0; i < 4; i++) {
        int r = r0 + ty * 4 + i;
        float4 v = make_float4(acc[i][0], acc[i][1], acc[i][2], acc[i][3]);
        *(float4*)&g_ctrl[(size_t)kz * BR + r * 64 + tx * 4] = v;
    }
}

// ---------------------------------------------------------------------------
// Kernel 1b: reduce 4 partials [kz][r][b] and transpose -> g_gates [b][r].
// ---------------------------------------------------------------------------
__global__ __launch_bounds__(256) void ctrl_reduce_t()
{
    __shared__ float s[64 * 65];
    const int r0  = blockIdx.x * 64;
    const int tid = threadIdx.x;

    #pragma unroll
    for (int t = 0; t < 16; t++) {
        int i  = t * 256 + tid;
        int rr = i >> 6, b = i & 63;
        float v = 0.f;
        #pragma unroll
        for (int k = 0; k < KSPLIT; k++)
            v += g_ctrl[(size_t)k * BR + (r0 + rr) * 64 + b];
        s[rr * 65 + b] = v;
    }
    __syncthreads();

    #pragma unroll
    for (int t = 0; t < 16; t++) {
        int i  = t * 256 + tid;
        int b  = i >> 6, rr = i & 63;
        g_gates[(size_t)b * ROWS + r0 + rr] = s[rr * 65 + b];
    }
}

// ---------------------------------------------------------------------------
// Kernel 2: tensor-core vstm + cp.async state prefetch.
// Phase 1: gin tf32 (1 MMA). Phase 2: gout tf32 (1 MMA).
// Each warp prefetches its own 16x32 state sub-tile into s_st via cp.async,
// overlapped with staging + phase-1 MMAs; consumed after wait+syncwarp.
// ---------------------------------------------------------------------------
#define PIX_PAD 136
#define ST_PAD 132

__global__ __launch_bounds__(512, 2) void vstm_main(
    const float* __restrict__ inputs,     // [B, 32, 4096]
    const float* __restrict__ state,      // [B, 64, 4096]
    float* __restrict__ outputs,          // [B, 32, 4096]
    float* __restrict__ new_state)        // [B, 64, 4096]
{
    extern __shared__ float sm[];
    float* s_in  = sm;                          // [32][136] tf32-rounded
    float* s_t   = s_in + 32 * PIX_PAD;         // [64][136] tf32-rounded
    float* s_st  = s_t + 64 * PIX_PAD;          // [64][132] state prefetch
    float* s_gin = s_st + 64 * ST_PAD;          // [m][36] tf32
    float* s_got = s_gin + 64 * 36;             // [o][68] tf32
    float* s_f   = s_got + 32 * 68;             // [64] exact

    const int b    = blockIdx.y;
    const int p0   = blockIdx.x * 128;
    const int tid  = threadIdx.x;
    const int lane = tid & 31;
    const int w    = tid >> 5;       // 0..15
    const int g    = lane >> 2;      // 0..7
    const int tg   = lane & 3;       // 0..3

    const int m0 = (w & 3) * 16;     // phase-1 row tile of this warp
    const int pg = (w >> 2) * 32;    // phase-1 pixel group of this warp

    // ---- issue cp.async state prefetch FIRST (own warp's 16x32 sub-tile) ----
    {
        const float* stb = state + (size_t)b * (NM * HW) + p0;
        #pragma unroll
        for (int s = 0; s < 4; s++) {
            int seg = s * 32 + lane;            // 0..127
            int row = m0 + (seg >> 3);          // 16 rows
            int col = pg + (seg & 7) * 4;       // 8 segs of 4 floats
            cp_async16(smem_u32(&s_st[row * ST_PAD + col]),
                       &stb[(size_t)row * 4096 + col]);
        }
        asm volatile("cp.async.commit_group;");
    }

    // ---- stage gates (tf32-rounded; f exact) ----
    {
        const float* gc = g_gates + (size_t)b * ROWS;
        for (int i = tid; i < ROWS; i += 512) {
            float v = gc[i];
            if (i < 64) {
                s_f[i] = v;
            } else if (i < 64 + 2048) {
                int j = i - 64;                       // in_gates [m][c]
                s_gin[(j >> 5) * 36 + (j & 31)] = round_tf32(v);
            } else {
                int j = i - 2112;                     // out_gates [o][m]
                s_got[(j >> 6) * 68 + (j & 63)] = round_tf32(v);
            }
        }
    }

    // ---- stage input tile, tf32-rounded ----
    const float* inb = inputs + (size_t)b * (IC * HW) + p0;
    #pragma unroll
    for (int i = tid; i < 32 * 32; i += 512) {
        int c = i >> 5, p4 = i & 31;
        float4 v = *(const float4*)&inb[c * 4096 + p4 * 4];
        v.x = round_tf32(v.x); v.y = round_tf32(v.y);
        v.z = round_tf32(v.z); v.w = round_tf32(v.w);
        *(float4*)&s_in[c * PIX_PAD + p4 * 4] = v;
    }
    __syncthreads();

    // ==== phase 1: gated(64x128) = gin_tf32(64x32) @ in(32x128), 1 MMA ====
    {
        float d[4][4] = {};

        #pragma unroll
        for (int kk = 0; kk < 4; kk++) {
            const int k0 = kk * 8;
            uint32_t ah[4];
            ah[0] = __float_as_uint(s_gin[(m0 + g)     * 36 + k0 + tg]);
            ah[1] = __float_as_uint(s_gin[(m0 + g + 8) * 36 + k0 + tg]);
            ah[2] = __float_as_uint(s_gin[(m0 + g)     * 36 + k0 + tg + 4]);
            ah[3] = __float_as_uint(s_gin[(m0 + g + 8) * 36 + k0 + tg + 4]);

            #pragma unroll
            for (int u = 0; u < 4; u++) {
                const int pb = pg + u * 8;
                uint32_t bh[2];
                bh[0] = __float_as_uint(s_in[(k0 + tg)     * PIX_PAD + pb + g]);
                bh[1] = __float_as_uint(s_in[(k0 + tg + 4) * PIX_PAD + pb + g]);
                mma_tf32_u(d[u], ah, bh);
            }
        }

        // state prefetch must be visible (own warp's copies only)
        asm volatile("cp.async.wait_group 0;" ::: "memory");
        __syncwarp();

        const int r1 = m0 + g, r2 = r1 + 8;
        const float f1 = s_f[r1], f2 = s_f[r2];
        float* nsb = new_state + (size_t)b * (NM * HW) + p0;

        #pragma unroll
        for (int u = 0; u < 4; u++) {
            const int c2 = pg + u * 8 + 2 * tg;
            float2 st1 = *(const float2*)&s_st[r1 * ST_PAD + c2];
            float2 st2 = *(const float2*)&s_st[r2 * ST_PAD + c2];
            float2 ns1, ns2;
            ns1.x = fmaf(st1.x, f1, d[u][0]);
            ns1.y = fmaf(st1.y, f1, d[u][1]);
            ns2.x = fmaf(st2.x, f2, d[u][2]);
            ns2.y = fmaf(st2.y, f2, d[u][3]);
            *(float2*)&nsb[(size_t)r1 * 4096 + c2] = ns1;
            *(float2*)&nsb[(size_t)r2 * 4096 + c2] = ns2;
            float2 t1, t2;
            t1.x = round_tf32(tanh_fast(ns1.x));
            t1.y = round_tf32(tanh_fast(ns1.y));
            t2.x = round_tf32(tanh_fast(ns2.x));
            t2.y = round_tf32(tanh_fast(ns2.y));
            *(float2*)&s_t[r1 * PIX_PAD + c2] = t1;
            *(float2*)&s_t[r2 * PIX_PAD + c2] = t2;
        }
    }
    __syncthreads();

    // ==== phase 2: out(32x128) = gout_tf32(32x64) @ t(64x128), 1 MMA ====
    {
        const int o0  = (w & 1) * 16;
        const int pg2 = (w >> 1) * 16;
        float d[2][4] = {};

        #pragma unroll
        for (int kk = 0; kk < 8; kk++) {
            const int k0 = kk * 8;
            uint32_t ah[4];
            ah[0] = __float_as_uint(s_got[(o0 + g)     * 68 + k0 + tg]);
            ah[1] = __float_as_uint(s_got[(o0 + g + 8) * 68 + k0 + tg]);
            ah[2] = __float_as_uint(s_got[(o0 + g)     * 68 + k0 + tg + 4]);
            ah[3] = __float_as_uint(s_got[(o0 + g + 8) * 68 + k0 + tg + 4]);

            #pragma unroll
            for (int v = 0; v < 2; v++) {
                const int pb = pg2 + v * 8;
                uint32_t bh[2];
                bh[0] = __float_as_uint(s_t[(k0 + tg)     * PIX_PAD + pb + g]);
                bh[1] = __float_as_uint(s_t[(k0 + tg + 4) * PIX_PAD + pb + g]);
                mma_tf32_u(d[v], ah, bh);
            }
        }

        const int r1 = o0 + g, r2 = r1 + 8;
        float* ob = outputs + (size_t)b * (OC * HW) + p0;
        #pragma unroll
        for (int v = 0; v < 2; v++) {
            const int c2 = pg2 + v * 8 + 2 * tg;
            *(float2*)&ob[(size_t)r1 * 4096 + c2] = make_float2(d[v][0], d[v][1]);
            *(float2*)&ob[(size_t)r2 * 4096 + c2] = make_float2(d[v][2], d[v][3]);
        }
    }
}

// ---------------------------------------------------------------------------
extern "C" void kernel_launch(void* const* d_in, const int* in_sizes, int n_in,
                              void* d_out, int out_size) {
    const float* inputs   = (const float*)d_in[0];   // [64,32,64,64]
    const float* state    = (const float*)d_in[1];   // [64,64,64,64]
    const float* controls = (const float*)d_in[2];   // [64,512]
    const float* W        = (const float*)d_in[3];   // [4160,512]

    float* outputs   = (float*)d_out;
    float* new_state = outputs + OUT_ELEMS;

    ctrl_gemm<<<dim3(65, KSPLIT), 256>>>(controls, W);
    ctrl_reduce_t<<<65, 256>>>();

    const size_t smem = (32 * PIX_PAD + 64 * PIX_PAD + 64 * ST_PAD
                         + 64 * 36 + 32 * 68 + 64) * sizeof(float);
    cudaFuncSetAttribute(vstm_main, cudaFuncAttributeMaxDynamicSharedMemorySize, (int)smem);
    vstm_main<<<dim3(HW / 128, BATCH), 512, smem>>>(inputs, state, outputs, new_state);
}

// round 17
// speedup vs baseline: 1.2957x; 1.1739x over previous
#include <cuda_runtime.h>
#include <math.h>
#include <stdint.h>

#define BATCH 64
#define IC 32
#define OC 32
#define NM 64
#define HW 4096
#define CTRLD 512
#define ROWS 4160        // NF(64) + NI(2048) + NO(2048)
#define KSPLIT 4
#define BR (BATCH * ROWS)
#define OUT_ELEMS (BATCH * OC * HW)

#define GLAY 4608        // per-batch gate layout: f[64] | gin[64*36] | gout[32*68]
#define GIN_OFF 64
#define GOT_OFF 2368

__device__ float g_ctrl[KSPLIT * BR];     // partials [kz][row][batch]
__device__ float g_glay[BATCH * GLAY];    // pre-laid-out gates per batch

__device__ __forceinline__ float tanh_fast(float x) {
    float y;
    asm("tanh.approx.f32 %0, %1;" : "=f"(y) : "f"(x));
    return y;
}
__device__ __forceinline__ float round_tf32(float x) {
    uint32_t h;
    asm("cvt.rna.tf32.f32 %0, %1;" : "=r"(h) : "f"(x));
    return __uint_as_float(h);
}
__device__ __forceinline__ void mma_tf32_u(float* d, const uint32_t* a, const uint32_t* b) {
    asm("mma.sync.aligned.m16n8k8.row.col.f32.tf32.tf32.f32 "
        "{%0,%1,%2,%3},{%4,%5,%6,%7},{%8,%9},{%0,%1,%2,%3};"
        : "+f"(d[0]), "+f"(d[1]), "+f"(d[2]), "+f"(d[3])
        : "r"(a[0]), "r"(a[1]), "r"(a[2]), "r"(a[3]), "r"(b[0]), "r"(b[1]));
}
__device__ __forceinline__ uint32_t smem_u32(const void* p) {
    return (uint32_t)__cvta_generic_to_shared(p);
}
__device__ __forceinline__ void cp_async16(uint32_t saddr, const void* gaddr) {
    asm volatile("cp.async.cg.shared.global [%0], [%1], 16;"
                 :: "r"(saddr), "l"(gaddr));
}

// ---------------------------------------------------------------------------
// Kernel 1: ctrl partials = controls @ W.T (grid 65 x 4). Measured-best config.
// ---------------------------------------------------------------------------
__global__ __launch_bounds__(256) void ctrl_gemm(
    const float* __restrict__ controls,   // [64, 512]
    const float* __restrict__ W)          // [4160, 512]
{
    __shared__ float sW[2][16 * 68];
    __shared__ float sC[2][16 * 68];

    const int r0    = blockIdx.x * 64;
    const int kz    = blockIdx.y;
    const int kbase = kz * (CTRLD / KSPLIT);
    const int tid   = threadIdx.x;
    const int ty    = tid >> 4;
    const int tx    = tid & 15;

    const int sr = tid >> 2;
    const int sk = (tid & 3) * 4;

    const float* wp = W + (size_t)(r0 + sr) * CTRLD + kbase + sk;
    const float* cp = controls + sr * CTRLD + kbase + sk;

    float acc[4][4] = {};

    {
        float4 wv = *(const float4*)wp;
        float4 cv = *(const float4*)cp;
        sW[0][(sk + 0) * 68 + sr] = wv.x;
        sW[0][(sk + 1) * 68 + sr] = wv.y;
        sW[0][(sk + 2) * 68 + sr] = wv.z;
        sW[0][(sk + 3) * 68 + sr] = wv.w;
        sC[0][(sk + 0) * 68 + sr] = cv.x;
        sC[0][(sk + 1) * 68 + sr] = cv.y;
        sC[0][(sk + 2) * 68 + sr] = cv.z;
        sC[0][(sk + 3) * 68 + sr] = cv.w;
    }
    __syncthreads();

    #pragma unroll
    for (int c = 0; c < 8; c++) {
        const int cur = c & 1;
        const int nxt = cur ^ 1;

        float4 wv, cv;
        if (c < 7) {
            wv = *(const float4*)(wp + (c + 1) * 16);
            cv = *(const float4*)(cp + (c + 1) * 16);
        }

        #pragma unroll
        for (int k = 0; k < 16; k++) {
            float4 a  = *(const float4*)&sW[cur][k * 68 + ty * 4];
            float4 bb = *(const float4*)&sC[cur][k * 68 + tx * 4];
            float av[4] = {a.x, a.y, a.z, a.w};
            float bv[4] = {bb.x, bb.y, bb.z, bb.w};
            #pragma unroll
            for (int i = 0; i < 4; i++)
                #pragma unroll
                for (int j = 0; j < 4; j++)
                    acc[i][j] = fmaf(av[i], bv[j], acc[i][j]);
        }

        if (c < 7) {
            sW[nxt][(sk + 0) * 68 + sr] = wv.x;
            sW[nxt][(sk + 1) * 68 + sr] = wv.y;
            sW[nxt][(sk + 2) * 68 + sr] = wv.z;
            sW[nxt][(sk + 3) * 68 + sr] = wv.w;
            sC[nxt][(sk + 0) * 68 + sr] = cv.x;
            sC[nxt][(sk + 1) * 68 + sr] = cv.y;
            sC[nxt][(sk + 2) * 68 + sr] = cv.z;
            sC[nxt][(sk + 3) * 68 + sr] = cv.w;
            __syncthreads();
        }
    }

    #pragma unroll
    for (int i = 0; i < 4; i++) {
        int r = r0 + ty * 4 + i;
        float4 v = make_float4(acc[i][0], acc[i][1], acc[i][2], acc[i][3]);
        *(float4*)&g_ctrl[(size_t)kz * BR + r * 64 + tx * 4] = v;
    }
}

// ---------------------------------------------------------------------------
// Kernel 1b: reduce 4 partials [kz][r][b], transpose, round, and scatter into
// the per-batch SMEM-image layout g_glay[b][GLAY].
// ---------------------------------------------------------------------------
__global__ __launch_bounds__(256) void ctrl_reduce_t()
{
    __shared__ float s[64 * 65];
    const int r0  = blockIdx.x * 64;
    const int tid = threadIdx.x;

    #pragma unroll
    for (int t = 0; t < 16; t++) {
        int i  = t * 256 + tid;
        int rr = i >> 6, b = i & 63;
        float v = 0.f;
        #pragma unroll
        for (int k = 0; k < KSPLIT; k++)
            v += g_ctrl[(size_t)k * BR + (r0 + rr) * 64 + b];
        s[rr * 65 + b] = v;
    }
    __syncthreads();

    #pragma unroll
    for (int t = 0; t < 16; t++) {
        int i  = t * 256 + tid;
        int b  = i >> 6, rr = i & 63;    // consecutive tid -> consecutive rr
        int r  = r0 + rr;
        float v = s[rr * 65 + b];
        size_t base = (size_t)b * GLAY;
        if (r < 64) {
            g_glay[base + r] = v;                                  // exact
        } else if (r < 2112) {
            int j = r - 64;                                        // gin [m][36]
            g_glay[base + GIN_OFF + (j >> 5) * 36 + (j & 31)] = round_tf32(v);
        } else {
            int j = r - 2112;                                      // gout [o][68]
            g_glay[base + GOT_OFF + (j >> 6) * 68 + (j & 63)] = round_tf32(v);
        }
    }
}

// ---------------------------------------------------------------------------
// Kernel 2: tensor-core vstm. Gate staging = contiguous vector copy of the
// pre-laid-out image. Mid-kernel block sync replaced by per-quad named
// barriers (quad q = 4 warps sharing one 32-pixel group).
// ---------------------------------------------------------------------------
#define PIX_PAD 136
#define ST_PAD 132

__global__ __launch_bounds__(512, 2) void vstm_main(
    const float* __restrict__ inputs,     // [B, 32, 4096]
    const float* __restrict__ state,      // [B, 64, 4096]
    float* __restrict__ outputs,          // [B, 32, 4096]
    float* __restrict__ new_state)        // [B, 64, 4096]
{
    extern __shared__ float sm[];
    float* s_gate = sm;                        // [4608] = f | gin | gout
    float* s_in   = s_gate + GLAY;             // [32][136] tf32-rounded
    float* s_t    = s_in + 32 * PIX_PAD;       // [64][136] tf32-rounded
    float* s_st   = s_t + 64 * PIX_PAD;        // [64][132] state prefetch

    float* s_f   = s_gate;
    float* s_gin = s_gate + GIN_OFF;           // [m][36]
    float* s_got = s_gate + GOT_OFF;           // [o][68]

    const int b    = blockIdx.y;
    const int p0   = blockIdx.x * 128;
    const int tid  = threadIdx.x;
    const int lane = tid & 31;
    const int w    = tid >> 5;       // 0..15
    const int g    = lane >> 2;      // 0..7
    const int tg   = lane & 3;       // 0..3
    const int q    = w >> 2;         // quad 0..3 -> pixel group q*32

    const int m0 = (w & 3) * 16;     // phase-1 row tile
    const int pg = q * 32;           // phase-1 pixel group

    // ---- issue cp.async state prefetch FIRST (own warp's 16x32 sub-tile) ----
    {
        const float* stb = state + (size_t)b * (NM * HW) + p0;
        #pragma unroll
        for (int s = 0; s < 4; s++) {
            int seg = s * 32 + lane;            // 0..127
            int row = m0 + (seg >> 3);          // 16 rows
            int col = pg + (seg & 7) * 4;       // 8 segs of 4 floats
            cp_async16(smem_u32(&s_st[row * ST_PAD + col]),
                       &stb[(size_t)row * 4096 + col]);
        }
        asm volatile("cp.async.commit_group;");
    }

    // ---- stage gates: straight contiguous vector copy (pre-rounded) ----
    {
        const float* gl = g_glay + (size_t)b * GLAY;
        #pragma unroll
        for (int i = tid; i < GLAY / 4; i += 512) {   // 1152 float4 (incl. pad)
            *(float4*)&s_gate[i * 4] = *(const float4*)&gl[i * 4];
        }
    }

    // ---- stage input tile, tf32-rounded ----
    const float* inb = inputs + (size_t)b * (IC * HW) + p0;
    #pragma unroll
    for (int i = tid; i < 32 * 32; i += 512) {
        int c = i >> 5, p4 = i & 31;
        float4 v = *(const float4*)&inb[c * 4096 + p4 * 4];
        v.x = round_tf32(v.x); v.y = round_tf32(v.y);
        v.z = round_tf32(v.z); v.w = round_tf32(v.w);
        *(float4*)&s_in[c * PIX_PAD + p4 * 4] = v;
    }
    __syncthreads();

    // ==== phase 1: gated(64x128) = gin_tf32(64x32) @ in(32x128), 1 MMA ====
    {
        float d[4][4] = {};

        #pragma unroll
        for (int kk = 0; kk < 4; kk++) {
            const int k0 = kk * 8;
            uint32_t ah[4];
            ah[0] = __float_as_uint(s_gin[(m0 + g)     * 36 + k0 + tg]);
            ah[1] = __float_as_uint(s_gin[(m0 + g + 8) * 36 + k0 + tg]);
            ah[2] = __float_as_uint(s_gin[(m0 + g)     * 36 + k0 + tg + 4]);
            ah[3] = __float_as_uint(s_gin[(m0 + g + 8) * 36 + k0 + tg + 4]);

            #pragma unroll
            for (int u = 0; u < 4; u++) {
                const int pb = pg + u * 8;
                uint32_t bh[2];
                bh[0] = __float_as_uint(s_in[(k0 + tg)     * PIX_PAD + pb + g]);
                bh[1] = __float_as_uint(s_in[(k0 + tg + 4) * PIX_PAD + pb + g]);
                mma_tf32_u(d[u], ah, bh);
            }
        }

        // state prefetch must be visible (own warp's copies only)
        asm volatile("cp.async.wait_group 0;" ::: "memory");
        __syncwarp();

        const int r1 = m0 + g, r2 = r1 + 8;
        const float f1 = s_f[r1], f2 = s_f[r2];
        float* nsb = new_state + (size_t)b * (NM * HW) + p0;

        #pragma unroll
        for (int u = 0; u < 4; u++) {
            const int c2 = pg + u * 8 + 2 * tg;
            float2 st1 = *(const float2*)&s_st[r1 * ST_PAD + c2];
            float2 st2 = *(const float2*)&s_st[r2 * ST_PAD + c2];
            float2 ns1, ns2;
            ns1.x = fmaf(st1.x, f1, d[u][0]);
            ns1.y = fmaf(st1.y, f1, d[u][1]);
            ns2.x = fmaf(st2.x, f2, d[u][2]);
            ns2.y = fmaf(st2.y, f2, d[u][3]);
            *(float2*)&nsb[(size_t)r1 * 4096 + c2] = ns1;
            *(float2*)&nsb[(size_t)r2 * 4096 + c2] = ns2;
            float2 t1, t2;
            t1.x = round_tf32(tanh_fast(ns1.x));
            t1.y = round_tf32(tanh_fast(ns1.y));
            t2.x = round_tf32(tanh_fast(ns2.x));
            t2.y = round_tf32(tanh_fast(ns2.y));
            *(float2*)&s_t[r1 * PIX_PAD + c2] = t1;
            *(float2*)&s_t[r2 * PIX_PAD + c2] = t2;
        }
    }

    // per-quad barrier: only the 4 warps sharing this 32-pixel group
    asm volatile("bar.sync %0, %1;" :: "r"(q + 1), "r"(128) : "memory");

    // ==== phase 2: out(32x128) = gout_tf32(32x64) @ t(64x128), 1 MMA ====
    // quad-local pixel tiling: pg2 in {q*32, q*32+16}
    {
        const int o0  = (w & 1) * 16;
        const int pg2 = q * 32 + ((w >> 1) & 1) * 16;
        float d[2][4] = {};

        #pragma unroll
        for (int kk = 0; kk < 8; kk++) {
            const int k0 = kk * 8;
            uint32_t ah[4];
            ah[0] = __float_as_uint(s_got[(o0 + g)     * 68 + k0 + tg]);
            ah[1] = __float_as_uint(s_got[(o0 + g + 8) * 68 + k0 + tg]);
            ah[2] = __float_as_uint(s_got[(o0 + g)     * 68 + k0 + tg + 4]);
            ah[3] = __float_as_uint(s_got[(o0 + g + 8) * 68 + k0 + tg + 4]);

            #pragma unroll
            for (int v = 0; v < 2; v++) {
                const int pb = pg2 + v * 8;
                uint32_t bh[2];
                bh[0] = __float_as_uint(s_t[(k0 + tg)     * PIX_PAD + pb + g]);
                bh[1] = __float_as_uint(s_t[(k0 + tg + 4) * PIX_PAD + pb + g]);
                mma_tf32_u(d[v], ah, bh);
            }
        }

        const int r1 = o0 + g, r2 = r1 + 8;
        float* ob = outputs + (size_t)b * (OC * HW) + p0;
        #pragma unroll
        for (int v = 0; v < 2; v++) {
            const int c2 = pg2 + v * 8 + 2 * tg;
            *(float2*)&ob[(size_t)r1 * 4096 + c2] = make_float2(d[v][0], d[v][1]);
            *(float2*)&ob[(size_t)r2 * 4096 + c2] = make_float2(d[v][2], d[v][3]);
        }
    }
}

// ---------------------------------------------------------------------------
extern "C" void kernel_launch(void* const* d_in, const int* in_sizes, int n_in,
                              void* d_out, int out_size) {
    const float* inputs   = (const float*)d_in[0];   // [64,32,64,64]
    const float* state    = (const float*)d_in[1];   // [64,64,64,64]
    const float* controls = (const float*)d_in[2];   // [64,512]
    const float* W        = (const float*)d_in[3];   // [4160,512]

    float* outputs   = (float*)d_out;
    float* new_state = outputs + OUT_ELEMS;

    ctrl_gemm<<<dim3(65, KSPLIT), 256>>>(controls, W);
    ctrl_reduce_t<<<65, 256>>>();

    const size_t smem = (GLAY + 32 * PIX_PAD + 64 * PIX_PAD + 64 * ST_PAD)
                        * sizeof(float);
    cudaFuncSetAttribute(vstm_main, cudaFuncAttributeMaxDynamicSharedMemorySize, (int)smem);
    vstm_main<<<dim3(HW / 128, BATCH), 512, smem>>>(inputs, state, outputs, new_state);
}